// round 15
// baseline (speedup 1.0000x reference)
#include <cuda_runtime.h>
#include <cuda_bf16.h>
#include <cstdint>

#define T_STEPS 1024
#define BATCH   128
#define FEAT    88
#define HID     1024
#define CLS     88
#define NCTA    128
#define NTHR    256
#define MT      64            // batch rows per CTA
#define UPC     16            // hidden units per CTA -> 64 gate cols
#define CW      128           // h chunk width (K cols)
#define WS_STRIDE 1056        // resident-W row stride (halfs): 16-word/row shift -> LDS128 conflict-free
#define ASTR    136           // A-tile row stride (halfs)
#define NBUF    4
#define GBSTR   72            // gx-slice row stride (halfs)
#define FC_ASTR 72

// ---------------- device globals ----------------
__device__ __nv_bfloat16 g_Wc[(size_t)4096 * HID];                 // bf16 W_hh
__device__ __nv_bfloat16 g_Wxb[(size_t)4096 * 96];                 // bf16 W_ih padded to 96
__device__ __nv_bfloat16 g_Wfcb[(size_t)CLS * HID];
__device__ float         g_bsum[4096];
__device__ __nv_bfloat16 g_xb[(size_t)T_STEPS * BATCH * FEAT];
__device__ __nv_bfloat16 g_gx[(size_t)T_STEPS * BATCH * 4096];     // precomputed x@Wih^T + bias
__device__ __nv_bfloat16 g_h[2][BATCH * HID];
__device__ __nv_bfloat16 g_Hall[(size_t)T_STEPS * BATCH * HID];
__device__ int           g_flag[NCTA * 4];

// ---------------- helpers ----------------
__device__ __forceinline__ unsigned smem_u32(const void* p) {
    return (unsigned)__cvta_generic_to_shared(p);
}
__device__ __forceinline__ float sigmoidf_(float x) {
    return 1.0f / (1.0f + __expf(-x));
}
__device__ __forceinline__ float tanhf_(float x) {
    float ax = fabsf(x);
    float e  = __expf(-2.0f * ax);
    float r  = (1.0f - e) / (1.0f + e);
    return (x < 0.0f) ? -r : r;
}

#define MMA_BF16(ACC, A0, A1, A2, A3, B0, B1)                                             \
    asm volatile(                                                                         \
        "mma.sync.aligned.m16n8k16.row.col.f32.bf16.bf16.f32 "                            \
        "{%0,%1,%2,%3}, {%4,%5,%6,%7}, {%8,%9}, {%0,%1,%2,%3};\n"                         \
        : "+f"((ACC)[0]), "+f"((ACC)[1]), "+f"((ACC)[2]), "+f"((ACC)[3])                  \
        : "r"(A0), "r"(A1), "r"(A2), "r"(A3), "r"(B0), "r"(B1))

#define LDMATRIX_X4(R0, R1, R2, R3, ADDR)                                                 \
    asm volatile("ldmatrix.sync.aligned.m8n8.x4.shared.b16 {%0,%1,%2,%3}, [%4];\n"        \
                 : "=r"(R0), "=r"(R1), "=r"(R2), "=r"(R3) : "r"(ADDR))

#define LDS128(R0, R1, R2, R3, ADDR)                                                      \
    asm volatile("ld.shared.v4.u32 {%0,%1,%2,%3}, [%4];"                                  \
                 : "=r"(R0), "=r"(R1), "=r"(R2), "=r"(R3) : "r"(ADDR))

#define CP_ASYNC16(DST, SRC)                                                              \
    asm volatile("cp.async.cg.shared.global [%0], [%1], 16;\n" :: "r"(DST), "l"(SRC))
#define CP_COMMIT  asm volatile("cp.async.commit_group;\n")
#define CP_WAIT(N) asm volatile("cp.async.wait_group %0;\n" :: "n"(N))

// ---------------- prep kernels (launch order: init, prep_all, gx, lstm(4th), fc) ----------------
__global__ void init_kernel() {
    int idx = blockIdx.x * blockDim.x + threadIdx.x;
    uint4 z = make_uint4(0u, 0u, 0u, 0u);
    for (int i = idx; i < 32768; i += gridDim.x * blockDim.x)
        reinterpret_cast<uint4*>(g_h)[i] = z;
    if (idx < NCTA * 4) g_flag[idx] = 0;
}

__global__ void prep_all_kernel(const float* __restrict__ x,
                                const float* __restrict__ Wih, const float* __restrict__ Whh,
                                const float* __restrict__ bih, const float* __restrict__ bhh,
                                const float* __restrict__ Wfc) {
    size_t idx = (size_t)blockIdx.x * blockDim.x + threadIdx.x;
    if (idx < (size_t)4096 * HID)
        g_Wc[idx] = __float2bfloat16(Whh[idx]);
    if (idx < (size_t)4096 * 96) {
        int n = (int)(idx / 96), k = (int)(idx % 96);
        float v = (k < FEAT) ? Wih[(size_t)n * FEAT + k] : 0.f;
        g_Wxb[idx] = __float2bfloat16(v);
    }
    if (idx < 4096) g_bsum[idx] = bih[idx] + bhh[idx];
    if (idx < (size_t)CLS * HID) g_Wfcb[idx] = __float2bfloat16(Wfc[idx]);
    if (idx < (size_t)T_STEPS * BATCH * FEAT)
        g_xb[idx] = __float2bfloat16(x[idx]);
}

// gx = x @ Wih^T + bsum, bf16. grid = 2048 row-tiles (64 rows), 256 threads.
__global__ void __launch_bounds__(256)
gx_kernel()
{
    extern __shared__ char gs[];
    __nv_bfloat16* Ax = reinterpret_cast<__nv_bfloat16*>(gs);            // 64 x 104
    __nv_bfloat16* Bw = Ax + 64 * 104;                                   // 256 x 104

    const int tid  = threadIdx.x;
    const int lane = tid & 31, wid = tid >> 5;
    const int r0   = blockIdx.x * 64;
    const int rowt = (wid & 3) * 16;
    const int colg = (wid >> 2) * 128;

    const unsigned ax_u = smem_u32(Ax);
    const unsigned bw_u = smem_u32(Bw);

    for (int i = tid; i < 64 * 4; i += 256)
        reinterpret_cast<unsigned*>(Ax)[(i >> 2) * 52 + 44 + (i & 3)] = 0u;
    for (int i = tid; i < 64 * 11; i += 256) {
        int row = i / 11, seg = i % 11;
        unsigned dst = ax_u + (unsigned)((row * 104 + seg * 8) * 2);
        CP_ASYNC16(dst, g_xb + (size_t)(r0 + row) * FEAT + seg * 8);
    }
    CP_COMMIT;

    for (int ci = 0; ci < 16; ++ci) {
        const int c0 = ci * 256;
        for (int i = tid; i < 256 * 12; i += 256) {
            int row = i / 12, seg = i % 12;
            unsigned dst = bw_u + (unsigned)((row * 104 + seg * 8) * 2);
            CP_ASYNC16(dst, g_Wxb + (size_t)(c0 + row) * 96 + seg * 8);
        }
        CP_COMMIT;
        CP_WAIT(0);
        __syncthreads();

        float acc[16][4];
#pragma unroll
        for (int i = 0; i < 16; ++i)
#pragma unroll
            for (int j = 0; j < 4; ++j) acc[i][j] = 0.f;

#pragma unroll
        for (int ks = 0; ks < 6; ++ks) {
            int kk = ks * 16;
            unsigned a0, a1, a2, a3;
            unsigned addr = ax_u +
                (unsigned)(((rowt + (lane & 15)) * 104 + kk + ((lane >> 4) << 3)) * 2);
            LDMATRIX_X4(a0, a1, a2, a3, addr);
#pragma unroll
            for (int nf = 0; nf < 16; ++nf) {
                int n = colg + nf * 8 + (lane >> 2);
                unsigned baddr = bw_u + (unsigned)((n * 104 + kk + ((lane & 3) << 1)) * 2);
                unsigned b0r, b1r;
                asm volatile("ld.shared.b32 %0, [%1];" : "=r"(b0r) : "r"(baddr));
                asm volatile("ld.shared.b32 %0, [%1];" : "=r"(b1r) : "r"(baddr + 16));
                MMA_BF16(acc[nf], a0, a1, a2, a3, b0r, b1r);
            }
        }
        __syncthreads();

#pragma unroll
        for (int half = 0; half < 2; ++half) {
            int r = rowt + (lane >> 2) + half * 8;
            size_t rbase = (size_t)(r0 + r) * 4096;
#pragma unroll
            for (int nf = 0; nf < 16; ++nf) {
                int c = c0 + colg + nf * 8 + ((lane & 3) << 1);
                float v0 = acc[nf][half * 2 + 0] + __ldg(g_bsum + c);
                float v1 = acc[nf][half * 2 + 1] + __ldg(g_bsum + c + 1);
                __nv_bfloat162 b2 = __floats2bfloat162_rn(v0, v1);
                *reinterpret_cast<unsigned*>(&g_gx[rbase + c]) =
                    *reinterpret_cast<unsigned*>(&b2);
            }
        }
    }
}

// ---------------- persistent LSTM kernel ----------------
// R14 chassis + (1) K-pair permuted W so each B fragment pair is ONE LDS128
//               + (2) two-phase barrier: wait chunk-1's 8 producers, stage(1),
//                     then wait remaining while stage(1) is in flight.
// Column (gate,unit) permutation unchanged: SMEM col c: gate g = (c&1)+2*((c>>3)&1),
// unit u = 4*(c>>4) + ((c>>1)&3)  -> in-register LSTM cell.
// K-direction: dst word j (row-local): block=j>>4, jj=j&15, q=jj>>2, e=jj&3;
// src word = (2*block + (e>>1))*8 + q + 4*(e&1)   (so LDS128 at block*64+q*16
// yields b0,b1 for ks=2*block and 2*block+1).
__global__ void __launch_bounds__(NTHR, 1)
lstm_kernel(const int* __restrict__ lens)
{
    extern __shared__ char smem_raw[];
    __nv_bfloat16* Ws  = reinterpret_cast<__nv_bfloat16*>(smem_raw);        // 64 * WS_STRIDE
    __nv_bfloat16* As  = Ws + 64 * WS_STRIDE;                               // NBUF * 64 * ASTR
    __nv_bfloat16* Gb  = As + NBUF * 64 * ASTR;                             // 64 * GBSTR
    int*   len_s       = reinterpret_cast<int*>(Gb + 64 * GBSTR);           // 64

    const int tid   = threadIdx.x;
    const int bid   = blockIdx.x;
    const int cta_m = bid & 1;
    const int cta_n = bid >> 1;
    const int b0    = cta_m * MT;
    const int hid0  = cta_n * UPC;

    // resident W slice: (gate,unit) column permutation + K-pair word permutation
    for (int i = tid; i < 64 * (HID / 2); i += NTHR) {
        int n = i / (HID / 2), j = i % (HID / 2);
        int block = j >> 4, jj = j & 15;
        int q = jj >> 2, e = jj & 3;
        int g16 = 2 * block + (e >> 1);
        int sq  = q + 4 * (e & 1);
        int g = (n & 1) + 2 * ((n >> 3) & 1);
        int u = 4 * (n >> 4) + ((n >> 1) & 3);
        const unsigned* src = reinterpret_cast<const unsigned*>(
                g_Wc + (size_t)(g * HID + hid0 + u) * HID);
        reinterpret_cast<unsigned*>(Ws + (size_t)n * WS_STRIDE)[j] = src[g16 * 8 + sq];
    }
    if (tid < 64) len_s[tid] = lens[b0 + tid];
    __syncthreads();

    const int lane = tid & 31, wid = tid >> 5;
    const int wm = wid & 1;        // 0..1
    const int wn = wid >> 1;       // 0..3 : units 4wn..4wn+3
    const int u_loc = 4 * wn + (lane & 3);

    // balanced row blocks: wm0 -> {0, 48}, wm1 -> {16, 32}
    const int rb0 = 16 * wm;
    const int rb1 = 48 - 16 * wm;

    const unsigned ws_u = smem_u32(Ws);
    const unsigned as_u = smem_u32(As);
    const unsigned gb_u = smem_u32(Gb);

    const bool watcher = (tid < 64);
    int* const my_fp   = &g_flag[(((tid & 63) << 1) | cta_m) << 2];

    const int len0 = len_s[0];
    const int lt0  = len_s[rb0];
    const int lt1  = len_s[rb1];

    int rown[4], lenr[4];
#pragma unroll
    for (int mi = 0; mi < 2; ++mi)
#pragma unroll
        for (int h2 = 0; h2 < 2; ++h2) {
            int r = (mi == 0 ? rb0 : rb1) + (lane >> 2) + 8 * h2;
            rown[2 * mi + h2] = r;
            lenr[2 * mi + h2] = len_s[r];
        }

    float hreg[4] = {0.f, 0.f, 0.f, 0.f};
    float creg[4] = {0.f, 0.f, 0.f, 0.f};

    for (int t = 0; t < T_STEPS; ++t) {
        const __nv_bfloat16* __restrict__ h_cur = g_h[t & 1];
        __nv_bfloat16* __restrict__ h_nxt = g_h[(t & 1) ^ 1];

        if (t >= len0) {
            if (tid == 0) {
                asm volatile("membar.gl;" ::: "memory");
                __stcg(&g_flag[bid << 2], T_STEPS);
            }
            CP_WAIT(0);
            break;
        }

        // stage gx slice for step t (h-independent, pre-barrier)
        {
#pragma unroll
            for (int r = 0; r < 2; ++r) {
                int slot = tid + r * NTHR;          // 0..511 = 64 rows x 8 segs
                int row = slot >> 3, seg = slot & 7;
                int g = seg >> 1, half8 = seg & 1;
                unsigned dst = gb_u + (unsigned)((row * GBSTR + g * 16 + half8 * 8) * 2);
                CP_ASYNC16(dst, g_gx + ((size_t)t * BATCH + b0 + row) * 4096 +
                                g * HID + hid0 + half8 * 8);
            }
            CP_COMMIT;
        }

        auto stage = [&](int s) {
            unsigned dstb = as_u + (unsigned)((s & 3) * 64 * ASTR * 2);
#pragma unroll
            for (int r = 0; r < 4; ++r) {
                int slot = tid + r * NTHR;          // 1024 slots = 64 rows x 16 seg
                int row = slot >> 4, c16 = slot & 15;
                unsigned dst = dstb + (unsigned)((row * ASTR + c16 * 8) * 2);
                CP_ASYNC16(dst, h_cur + (size_t)(b0 + row) * HID + (s - 1) * CW + c16 * 8);
            }
            CP_COMMIT;
        };

        // two-phase half-barrier
        if (t > 0) {
            int fv = 0x7fffffff;
            if (watcher)
                asm volatile("ld.acquire.gpu.global.b32 %0, [%1];" : "=r"(fv) : "l"(my_fp) : "memory");
            // phase A: chunk-1 producers only (cta_n 0..7 of this half)
            for (;;) {
                if (__syncthreads_count((tid >= 8) || (fv >= t)) == NTHR) break;
                if (tid < 8 && fv < t)
                    asm volatile("ld.acquire.gpu.global.b32 %0, [%1];" : "=r"(fv) : "l"(my_fp) : "memory");
            }
            stage(1);                               // c1 load overlaps phase B
            // phase B: all 64 producers
            for (;;) {
                if (__syncthreads_count(fv >= t) == NTHR) break;
                if (watcher && fv < t)
                    asm volatile("ld.acquire.gpu.global.b32 %0, [%1];" : "=r"(fv) : "l"(my_fp) : "memory");
            }
            stage(2);
            stage(3);
        } else {
            stage(1); stage(2); stage(3);
        }

        float acc[2][2][4];
#pragma unroll
        for (int a = 0; a < 2; ++a)
#pragma unroll
            for (int b = 0; b < 2; ++b)
#pragma unroll
                for (int c = 0; c < 4; ++c) acc[a][b][c] = 0.f;

        const bool act1 = (t < lt1);
        const bool act0 = (t < lt0);

#pragma unroll
        for (int s = 1; s <= 8; ++s) {
            if (s <= 6)      { CP_WAIT(2); }
            else if (s == 7) { CP_WAIT(1); }
            else             { CP_WAIT(0); }
            __syncthreads();
            if (s + 3 <= 8) stage(s + 3);

            const int blk0 = ((s - 1) * CW) >> 5;   // 32-half block index base
            const unsigned abase = as_u + (unsigned)((s & 3) * 64 * ASTR * 2);

            if (act1) {
#pragma unroll
                for (int kp = 0; kp < 4; ++kp) {
                    const int kk0 = kp * 32;
                    unsigned a0r[2][4], a1r[2][4];
#pragma unroll
                    for (int e = 0; e < 2; ++e) {
                        unsigned addr0 = abase +
                            (unsigned)(((rb0 + (lane & 15)) * ASTR + kk0 + e * 16 +
                                        ((lane >> 4) << 3)) * 2);
                        LDMATRIX_X4(a0r[e][0], a0r[e][1], a0r[e][2], a0r[e][3], addr0);
                        LDMATRIX_X4(a1r[e][0], a1r[e][1], a1r[e][2], a1r[e][3],
                                    addr0 + (unsigned)((rb1 - rb0) * ASTR * 2));
                    }
#pragma unroll
                    for (int nf = 0; nf < 2; ++nf) {
                        int n = wn * 16 + nf * 8 + (lane >> 2);
                        unsigned baddr = ws_u + (unsigned)(n * (WS_STRIDE * 2) +
                                         (blk0 + kp) * 64 + ((lane & 3) << 4));
                        unsigned b0a, b1a, b0b, b1b;
                        LDS128(b0a, b1a, b0b, b1b, baddr);
                        MMA_BF16(acc[0][nf], a0r[0][0], a0r[0][1], a0r[0][2], a0r[0][3], b0a, b1a);
                        MMA_BF16(acc[1][nf], a1r[0][0], a1r[0][1], a1r[0][2], a1r[0][3], b0a, b1a);
                        MMA_BF16(acc[0][nf], a0r[1][0], a0r[1][1], a0r[1][2], a0r[1][3], b0b, b1b);
                        MMA_BF16(acc[1][nf], a1r[1][0], a1r[1][1], a1r[1][2], a1r[1][3], b0b, b1b);
                    }
                }
            } else if (act0) {
#pragma unroll
                for (int kp = 0; kp < 4; ++kp) {
                    const int kk0 = kp * 32;
                    unsigned a0r[2][4];
#pragma unroll
                    for (int e = 0; e < 2; ++e) {
                        unsigned addr0 = abase +
                            (unsigned)(((rb0 + (lane & 15)) * ASTR + kk0 + e * 16 +
                                        ((lane >> 4) << 3)) * 2);
                        LDMATRIX_X4(a0r[e][0], a0r[e][1], a0r[e][2], a0r[e][3], addr0);
                    }
#pragma unroll
                    for (int nf = 0; nf < 2; ++nf) {
                        int n = wn * 16 + nf * 8 + (lane >> 2);
                        unsigned baddr = ws_u + (unsigned)(n * (WS_STRIDE * 2) +
                                         (blk0 + kp) * 64 + ((lane & 3) << 4));
                        unsigned b0a, b1a, b0b, b1b;
                        LDS128(b0a, b1a, b0b, b1b, baddr);
                        MMA_BF16(acc[0][nf], a0r[0][0], a0r[0][1], a0r[0][2], a0r[0][3], b0a, b1a);
                        MMA_BF16(acc[0][nf], a0r[1][0], a0r[1][1], a0r[1][2], a0r[1][3], b0b, b1b);
                    }
                }
            }
        }
        // in-register LSTM cell (each thread owns 4 gates of unit u_loc)

        __nv_bfloat16 hb[4];
#pragma unroll
        for (int mi = 0; mi < 2; ++mi)
#pragma unroll
            for (int h2 = 0; h2 < 2; ++h2) {
                const int li = 2 * mi + h2;
                const int r  = rown[li];
                float gi = acc[mi][0][2 * h2]     + __bfloat162float(Gb[r * GBSTR + u_loc]);
                float gf = acc[mi][0][2 * h2 + 1] + __bfloat162float(Gb[r * GBSTR + 16 + u_loc]);
                float gg = acc[mi][1][2 * h2]     + __bfloat162float(Gb[r * GBSTR + 32 + u_loc]);
                float go = acc[mi][1][2 * h2 + 1] + __bfloat162float(Gb[r * GBSTR + 48 + u_loc]);
                float ii = sigmoidf_(gi);
                float ff = sigmoidf_(gf);
                float gt = tanhf_(gg);
                float oo = sigmoidf_(go);
                float cn = ff * creg[li] + ii * gt;
                float hn = oo * tanhf_(cn);
                bool  m  = t < lenr[li];
                float h2v = m ? hn : hreg[li];
                creg[li] = m ? cn : creg[li];
                hreg[li] = h2v;
                hb[li] = __float2bfloat16(h2v);
                if (t <= lenr[li])
                    h_nxt[(b0 + r) * HID + hid0 + u_loc] = hb[li];
            }

        __syncthreads();
        if (tid == 0) {
            asm volatile("membar.gl;" ::: "memory");
            __stcg(&g_flag[bid << 2], t + 1);
        }

        // g_Hall: off critical path
#pragma unroll
        for (int li = 0; li < 4; ++li) {
            if (t < lenr[li]) {
                int r = rown[li];
                g_Hall[((size_t)t * BATCH + b0 + r) * HID + hid0 + u_loc] = hb[li];
            }
        }
    }
}

// ---------------- FC head: logits + binary expansion ----------------
__global__ void __launch_bounds__(128)
fc_kernel(const int* __restrict__ lens, const float* __restrict__ bfc,
          float* __restrict__ out)
{
    __shared__ __nv_bfloat16 As[64 * FC_ASTR];
    __shared__ __nv_bfloat16 Bs[88 * FC_ASTR];

    const int tid  = threadIdx.x;
    const int lane = tid & 31, wid = tid >> 5;
    const int r0   = blockIdx.x * 64;

    float acc[11][4];
#pragma unroll
    for (int i = 0; i < 11; ++i)
#pragma unroll
        for (int j = 0; j < 4; ++j) acc[i][j] = 0.f;

    const unsigned as_u = smem_u32(As);
    const unsigned bs_u = smem_u32(Bs);

    for (int ch = 0; ch < 16; ++ch) {
        __syncthreads();
        const int k0 = ch * 64;
        for (int i = tid; i < 512; i += 128) {
            int row = i >> 3, c8 = i & 7;
            uint4 v = *(reinterpret_cast<const uint4*>(
                    g_Hall + (size_t)(r0 + row) * HID + k0) + c8);
            *(reinterpret_cast<uint4*>(As + row * FC_ASTR) + c8) = v;
        }
        for (int i = tid; i < 704; i += 128) {
            int row = i >> 3, c8 = i & 7;
            uint4 v = *(reinterpret_cast<const uint4*>(
                    g_Wfcb + (size_t)row * HID + k0) + c8);
            *(reinterpret_cast<uint4*>(Bs + row * FC_ASTR) + c8) = v;
        }
        __syncthreads();
#pragma unroll
        for (int ks = 0; ks < 4; ++ks) {
            int kk = ks * 16;
            unsigned a0, a1, a2, a3;
            unsigned addr = as_u +
                (unsigned)(((wid * 16 + (lane & 15)) * FC_ASTR + kk + ((lane >> 4) << 3)) * 2);
            LDMATRIX_X4(a0, a1, a2, a3, addr);
#pragma unroll
            for (int nf = 0; nf < 11; ++nf) {
                int n = nf * 8 + (lane >> 2);
                unsigned baddr = bs_u +
                    (unsigned)((n * FC_ASTR + kk + ((lane & 3) << 1)) * 2);
                unsigned b0r, b1r;
                asm volatile("ld.shared.b32 %0, [%1];" : "=r"(b0r) : "r"(baddr));
                asm volatile("ld.shared.b32 %0, [%1];" : "=r"(b1r) : "r"(baddr + 16));
                MMA_BF16(acc[nf], a0, a1, a2, a3, b0r, b1r);
            }
        }
    }

#pragma unroll
    for (int half = 0; half < 2; ++half) {
        int r  = wid * 16 + (lane >> 2) + half * 8;
        int tb = r0 + r;
        int t  = tb >> 7;
        int b  = tb & 127;
        bool m = t < __ldg(lens + b);
        size_t obase = ((size_t)b * T_STEPS + t) * CLS * 2;
#pragma unroll
        for (int nf = 0; nf < 11; ++nf) {
            int c = nf * 8 + ((lane & 3) << 1);
            float l0 = acc[nf][half * 2 + 0] + __ldg(bfc + c);
            float l1 = acc[nf][half * 2 + 1] + __ldg(bfc + c + 1);
            if (!m) { l0 = 0.f; l1 = 0.f; }
            float4 v = make_float4(l0, 1.f - l0, l1, 1.f - l1);
            *reinterpret_cast<float4*>(out + obase + (size_t)c * 2) = v;
        }
    }
}

// ---------------- launch ----------------
extern "C" void kernel_launch(void* const* d_in, const int* in_sizes, int n_in,
                              void* d_out, int out_size) {
    const float* x    = (const float*)d_in[0];
    const int*   lens = (const int*)d_in[1];    // int32 (JAX x64 disabled)
    const float* Wih  = (const float*)d_in[2];
    const float* Whh  = (const float*)d_in[3];
    const float* bih  = (const float*)d_in[4];
    const float* bhh  = (const float*)d_in[5];
    const float* Wfc  = (const float*)d_in[6];
    const float* bfc  = (const float*)d_in[7];
    float*       out  = (float*)d_out;
    (void)in_sizes; (void)n_in; (void)out_size;

    // launch order: init(1), prep_all(2), gx(3), lstm(4 = ncu slot), fc(5)
    init_kernel<<<64, 256>>>();
    {
        size_t tot = (size_t)T_STEPS * BATCH * FEAT;
        prep_all_kernel<<<(unsigned)((tot + 255) / 256), 256>>>(x, Wih, Whh, bih, bhh, Wfc);
    }
    {
        int gx_smem = (64 * 104 + 256 * 104) * 2;      // 66,560 B
        cudaFuncSetAttribute(gx_kernel, cudaFuncAttributeMaxDynamicSharedMemorySize, gx_smem);
        gx_kernel<<<(T_STEPS * BATCH) / 64, 256, gx_smem>>>();
    }

    int smem = 64 * WS_STRIDE * 2          // resident W slice   (135,168)
             + NBUF * 64 * ASTR * 2        // A-stage ring       (69,632)
             + 64 * GBSTR * 2              // gx slice           (9,216)
             + 64 * 4;                     // lengths
    cudaFuncSetAttribute(lstm_kernel, cudaFuncAttributeMaxDynamicSharedMemorySize, smem);
    lstm_kernel<<<NCTA, NTHR, smem>>>(lens);

    fc_kernel<<<(T_STEPS * BATCH) / 64, 128>>>(lens, bfc, out);
}

// round 16
// speedup vs baseline: 1.3633x; 1.3633x over previous
#include <cuda_runtime.h>
#include <cuda_bf16.h>
#include <cstdint>

#define T_STEPS 1024
#define BATCH   128
#define FEAT    88
#define HID     1024
#define CLS     88
#define NCTA    128
#define NTHR    256
#define MT      64            // batch rows per CTA
#define UPC     16            // hidden units per CTA -> 64 gate cols
#define CW      128           // h chunk width (K cols)
#define WS_STRIDE 1032        // resident-W row stride (halfs)
#define ASTR    136           // A-tile row stride (halfs)
#define NBUF    4
#define GBSTR   72            // gx-slice row stride (halfs)
#define FC_ASTR 72

// ---------------- device globals ----------------
__device__ __nv_bfloat16 g_Wc[(size_t)4096 * HID];                 // bf16 W_hh
__device__ __nv_bfloat16 g_Wxb[(size_t)4096 * 96];                 // bf16 W_ih padded to 96
__device__ __nv_bfloat16 g_Wfcb[(size_t)CLS * HID];
__device__ float         g_bsum[4096];
__device__ __nv_bfloat16 g_xb[(size_t)T_STEPS * BATCH * FEAT];
__device__ __nv_bfloat16 g_gx[(size_t)T_STEPS * BATCH * 4096];     // precomputed x@Wih^T + bias
__device__ __nv_bfloat16 g_h[2][BATCH * HID];
__device__ __nv_bfloat16 g_Hall[(size_t)T_STEPS * BATCH * HID];
__device__ int           g_flag[NCTA * 4];

// ---------------- helpers ----------------
__device__ __forceinline__ unsigned smem_u32(const void* p) {
    return (unsigned)__cvta_generic_to_shared(p);
}
__device__ __forceinline__ float sigmoidf_(float x) {
    return 1.0f / (1.0f + __expf(-x));
}
__device__ __forceinline__ float tanhf_(float x) {
    float ax = fabsf(x);
    float e  = __expf(-2.0f * ax);
    float r  = (1.0f - e) / (1.0f + e);
    return (x < 0.0f) ? -r : r;
}

#define MMA_BF16(ACC, A0, A1, A2, A3, B0, B1)                                             \
    asm volatile(                                                                         \
        "mma.sync.aligned.m16n8k16.row.col.f32.bf16.bf16.f32 "                            \
        "{%0,%1,%2,%3}, {%4,%5,%6,%7}, {%8,%9}, {%0,%1,%2,%3};\n"                         \
        : "+f"((ACC)[0]), "+f"((ACC)[1]), "+f"((ACC)[2]), "+f"((ACC)[3])                  \
        : "r"(A0), "r"(A1), "r"(A2), "r"(A3), "r"(B0), "r"(B1))

#define LDMATRIX_X4(R0, R1, R2, R3, ADDR)                                                 \
    asm volatile("ldmatrix.sync.aligned.m8n8.x4.shared.b16 {%0,%1,%2,%3}, [%4];\n"        \
                 : "=r"(R0), "=r"(R1), "=r"(R2), "=r"(R3) : "r"(ADDR))

#define LDS64(R0, R1, ADDR)                                                               \
    asm volatile("ld.shared.v2.u32 {%0,%1}, [%2];" : "=r"(R0), "=r"(R1) : "r"(ADDR))

#define CP_ASYNC16(DST, SRC)                                                              \
    asm volatile("cp.async.cg.shared.global [%0], [%1], 16;\n" :: "r"(DST), "l"(SRC))
#define CP_COMMIT  asm volatile("cp.async.commit_group;\n")
#define CP_WAIT(N) asm volatile("cp.async.wait_group %0;\n" :: "n"(N))

// ---------------- prep kernels (launch order: init, prep_all, gx, lstm(4th), fc) ----------------
__global__ void init_kernel() {
    int idx = blockIdx.x * blockDim.x + threadIdx.x;
    uint4 z = make_uint4(0u, 0u, 0u, 0u);
    for (int i = idx; i < 32768; i += gridDim.x * blockDim.x)
        reinterpret_cast<uint4*>(g_h)[i] = z;
    if (idx < NCTA * 4) g_flag[idx] = 0;
}

__global__ void prep_all_kernel(const float* __restrict__ x,
                                const float* __restrict__ Wih, const float* __restrict__ Whh,
                                const float* __restrict__ bih, const float* __restrict__ bhh,
                                const float* __restrict__ Wfc) {
    size_t idx = (size_t)blockIdx.x * blockDim.x + threadIdx.x;
    if (idx < (size_t)4096 * HID)
        g_Wc[idx] = __float2bfloat16(Whh[idx]);
    if (idx < (size_t)4096 * 96) {
        int n = (int)(idx / 96), k = (int)(idx % 96);
        float v = (k < FEAT) ? Wih[(size_t)n * FEAT + k] : 0.f;
        g_Wxb[idx] = __float2bfloat16(v);
    }
    if (idx < 4096) g_bsum[idx] = bih[idx] + bhh[idx];
    if (idx < (size_t)CLS * HID) g_Wfcb[idx] = __float2bfloat16(Wfc[idx]);
    if (idx < (size_t)T_STEPS * BATCH * FEAT)
        g_xb[idx] = __float2bfloat16(x[idx]);
}

// gx = x @ Wih^T + bsum, bf16. grid = 2048 row-tiles (64 rows), 256 threads.
__global__ void __launch_bounds__(256)
gx_kernel()
{
    extern __shared__ char gs[];
    __nv_bfloat16* Ax = reinterpret_cast<__nv_bfloat16*>(gs);            // 64 x 104
    __nv_bfloat16* Bw = Ax + 64 * 104;                                   // 256 x 104

    const int tid  = threadIdx.x;
    const int lane = tid & 31, wid = tid >> 5;
    const int r0   = blockIdx.x * 64;
    const int rowt = (wid & 3) * 16;
    const int colg = (wid >> 2) * 128;

    const unsigned ax_u = smem_u32(Ax);
    const unsigned bw_u = smem_u32(Bw);

    for (int i = tid; i < 64 * 4; i += 256)
        reinterpret_cast<unsigned*>(Ax)[(i >> 2) * 52 + 44 + (i & 3)] = 0u;
    for (int i = tid; i < 64 * 11; i += 256) {
        int row = i / 11, seg = i % 11;
        unsigned dst = ax_u + (unsigned)((row * 104 + seg * 8) * 2);
        CP_ASYNC16(dst, g_xb + (size_t)(r0 + row) * FEAT + seg * 8);
    }
    CP_COMMIT;

    for (int ci = 0; ci < 16; ++ci) {
        const int c0 = ci * 256;
        for (int i = tid; i < 256 * 12; i += 256) {
            int row = i / 12, seg = i % 12;
            unsigned dst = bw_u + (unsigned)((row * 104 + seg * 8) * 2);
            CP_ASYNC16(dst, g_Wxb + (size_t)(c0 + row) * 96 + seg * 8);
        }
        CP_COMMIT;
        CP_WAIT(0);
        __syncthreads();

        float acc[16][4];
#pragma unroll
        for (int i = 0; i < 16; ++i)
#pragma unroll
            for (int j = 0; j < 4; ++j) acc[i][j] = 0.f;

#pragma unroll
        for (int ks = 0; ks < 6; ++ks) {
            int kk = ks * 16;
            unsigned a0, a1, a2, a3;
            unsigned addr = ax_u +
                (unsigned)(((rowt + (lane & 15)) * 104 + kk + ((lane >> 4) << 3)) * 2);
            LDMATRIX_X4(a0, a1, a2, a3, addr);
#pragma unroll
            for (int nf = 0; nf < 16; ++nf) {
                int n = colg + nf * 8 + (lane >> 2);
                unsigned baddr = bw_u + (unsigned)((n * 104 + kk + ((lane & 3) << 1)) * 2);
                unsigned b0r, b1r;
                asm volatile("ld.shared.b32 %0, [%1];" : "=r"(b0r) : "r"(baddr));
                asm volatile("ld.shared.b32 %0, [%1];" : "=r"(b1r) : "r"(baddr + 16));
                MMA_BF16(acc[nf], a0, a1, a2, a3, b0r, b1r);
            }
        }
        __syncthreads();

#pragma unroll
        for (int half = 0; half < 2; ++half) {
            int r = rowt + (lane >> 2) + half * 8;
            size_t rbase = (size_t)(r0 + r) * 4096;
#pragma unroll
            for (int nf = 0; nf < 16; ++nf) {
                int c = c0 + colg + nf * 8 + ((lane & 3) << 1);
                float v0 = acc[nf][half * 2 + 0] + __ldg(g_bsum + c);
                float v1 = acc[nf][half * 2 + 1] + __ldg(g_bsum + c + 1);
                __nv_bfloat162 b2 = __floats2bfloat162_rn(v0, v1);
                *reinterpret_cast<unsigned*>(&g_gx[rbase + c]) =
                    *reinterpret_cast<unsigned*>(&b2);
            }
        }
    }
}

// ---------------- persistent LSTM kernel ----------------
// EXACT 9,886-us chassis (in-register cell via (gate,unit) column permutation,
// balanced row blocks {0,48}/{16,32}, LDS64 B loads, WS_STRIDE 1032) with ONE
// change: two-phase barrier (phase A = chunk-1's 8 producers -> stage(1)
// overlaps phase B's full 64-producer wait).
__global__ void __launch_bounds__(NTHR, 1)
lstm_kernel(const int* __restrict__ lens)
{
    extern __shared__ char smem_raw[];
    __nv_bfloat16* Ws  = reinterpret_cast<__nv_bfloat16*>(smem_raw);        // 64 * WS_STRIDE
    __nv_bfloat16* As  = Ws + 64 * WS_STRIDE;                               // NBUF * 64 * ASTR
    __nv_bfloat16* Gb  = As + NBUF * 64 * ASTR;                             // 64 * GBSTR
    int*   len_s       = reinterpret_cast<int*>(Gb + 64 * GBSTR);           // 64

    const int tid   = threadIdx.x;
    const int bid   = blockIdx.x;
    const int cta_m = bid & 1;
    const int cta_n = bid >> 1;
    const int b0    = cta_m * MT;
    const int hid0  = cta_n * UPC;

    // resident W slice with (gate,unit) column permutation + k-pair permutation
    for (int i = tid; i < 64 * (HID / 2); i += NTHR) {
        int n = i / (HID / 2), j = i % (HID / 2);
        int g16 = j >> 3, q = j & 7;
        int sp  = (q >> 1) + ((q & 1) << 2);
        int g = (n & 1) + 2 * ((n >> 3) & 1);
        int u = 4 * (n >> 4) + ((n >> 1) & 3);
        const unsigned* src = reinterpret_cast<const unsigned*>(
                g_Wc + (size_t)(g * HID + hid0 + u) * HID);
        reinterpret_cast<unsigned*>(Ws + (size_t)n * WS_STRIDE)[j] = src[g16 * 8 + sp];
    }
    if (tid < 64) len_s[tid] = lens[b0 + tid];
    __syncthreads();

    const int lane = tid & 31, wid = tid >> 5;
    const int wm = wid & 1;        // 0..1
    const int wn = wid >> 1;       // 0..3 : units 4wn..4wn+3
    const int u_loc = 4 * wn + (lane & 3);

    // balanced row blocks: wm0 -> {0, 48}, wm1 -> {16, 32}
    const int rb0 = 16 * wm;
    const int rb1 = 48 - 16 * wm;

    const unsigned ws_u = smem_u32(Ws);
    const unsigned as_u = smem_u32(As);
    const unsigned gb_u = smem_u32(Gb);

    const bool watcher = (tid < 64);
    int* const my_fp   = &g_flag[(((tid & 63) << 1) | cta_m) << 2];

    const int len0 = len_s[0];
    const int lt0  = len_s[rb0];               // tile mi=0 bound
    const int lt1  = len_s[rb1];               // tile mi=1 bound (<= lt0)

    // per-thread cell rows + lengths: li = 2*mi + half
    int rown[4], lenr[4];
#pragma unroll
    for (int mi = 0; mi < 2; ++mi)
#pragma unroll
        for (int h2 = 0; h2 < 2; ++h2) {
            int r = (mi == 0 ? rb0 : rb1) + (lane >> 2) + 8 * h2;
            rown[2 * mi + h2] = r;
            lenr[2 * mi + h2] = len_s[r];
        }

    float hreg[4] = {0.f, 0.f, 0.f, 0.f};
    float creg[4] = {0.f, 0.f, 0.f, 0.f};

    for (int t = 0; t < T_STEPS; ++t) {
        const __nv_bfloat16* __restrict__ h_cur = g_h[t & 1];
        __nv_bfloat16* __restrict__ h_nxt = g_h[(t & 1) ^ 1];

        // whole-CTA early exit: all rows of this half frozen
        if (t >= len0) {
            if (tid == 0) {
                asm volatile("membar.gl;" ::: "memory");
                __stcg(&g_flag[bid << 2], T_STEPS);
            }
            CP_WAIT(0);
            break;
        }

        // stage gx slice for step t (h-independent, pre-barrier)
        {
#pragma unroll
            for (int r = 0; r < 2; ++r) {
                int slot = tid + r * NTHR;          // 0..511 = 64 rows x 8 segs
                int row = slot >> 3, seg = slot & 7;
                int g = seg >> 1, half8 = seg & 1;
                unsigned dst = gb_u + (unsigned)((row * GBSTR + g * 16 + half8 * 8) * 2);
                CP_ASYNC16(dst, g_gx + ((size_t)t * BATCH + b0 + row) * 4096 +
                                g * HID + hid0 + half8 * 8);
            }
            CP_COMMIT;
        }

        auto stage = [&](int s) {
            unsigned dstb = as_u + (unsigned)((s & 3) * 64 * ASTR * 2);
#pragma unroll
            for (int r = 0; r < 4; ++r) {
                int slot = tid + r * NTHR;          // 1024 slots = 64 rows x 16 seg
                int row = slot >> 4, c16 = slot & 15;
                unsigned dst = dstb + (unsigned)((row * ASTR + c16 * 8) * 2);
                CP_ASYNC16(dst, h_cur + (size_t)(b0 + row) * HID + (s - 1) * CW + c16 * 8);
            }
            CP_COMMIT;
        };

        // two-phase half-barrier (the ONE change vs the 9,886-us kernel)
        if (t > 0) {
            int fv = 0x7fffffff;
            if (watcher)
                asm volatile("ld.acquire.gpu.global.b32 %0, [%1];" : "=r"(fv) : "l"(my_fp) : "memory");
            // phase A: only chunk-1's 8 producers (cta_n 0..7 of this half)
            for (;;) {
                if (__syncthreads_count((tid >= 8) || (fv >= t)) == NTHR) break;
                if (tid < 8 && fv < t)
                    asm volatile("ld.acquire.gpu.global.b32 %0, [%1];" : "=r"(fv) : "l"(my_fp) : "memory");
            }
            stage(1);                               // c1's L2 latency overlaps phase B
            // phase B: all 64 producers
            for (;;) {
                if (__syncthreads_count(fv >= t) == NTHR) break;
                if (watcher && fv < t)
                    asm volatile("ld.acquire.gpu.global.b32 %0, [%1];" : "=r"(fv) : "l"(my_fp) : "memory");
            }
            stage(2);
            stage(3);
        } else {
            stage(1); stage(2); stage(3);
        }

        float acc[2][2][4];
#pragma unroll
        for (int a = 0; a < 2; ++a)
#pragma unroll
            for (int b = 0; b < 2; ++b)
#pragma unroll
                for (int c = 0; c < 4; ++c) acc[a][b][c] = 0.f;

        const bool act1 = (t < lt1);
        const bool act0 = (t < lt0);

#pragma unroll
        for (int s = 1; s <= 8; ++s) {
            if (s <= 6)      { CP_WAIT(2); }
            else if (s == 7) { CP_WAIT(1); }
            else             { CP_WAIT(0); }
            __syncthreads();
            if (s + 3 <= 8) stage(s + 3);

            const int kcol = (s - 1) * CW;
            const unsigned abase = as_u + (unsigned)((s & 3) * 64 * ASTR * 2);

            if (act1) {
#pragma unroll
                for (int ks = 0; ks < 8; ++ks) {
                    const int kk = ks * 16;
                    const int kg = kcol + kk;
                    unsigned a0r[4], a1r[4], bfr[2][2];
                    unsigned addr0 = abase +
                        (unsigned)(((rb0 + (lane & 15)) * ASTR + kk + ((lane >> 4) << 3)) * 2);
                    LDMATRIX_X4(a0r[0], a0r[1], a0r[2], a0r[3], addr0);
                    LDMATRIX_X4(a1r[0], a1r[1], a1r[2], a1r[3],
                                addr0 + (unsigned)((rb1 - rb0) * ASTR * 2));
#pragma unroll
                    for (int nf = 0; nf < 2; ++nf) {
                        int n = wn * 16 + nf * 8 + (lane >> 2);
                        unsigned baddr = ws_u +
                            (unsigned)((n * WS_STRIDE + kg) * 2) + ((lane & 3) << 3);
                        LDS64(bfr[nf][0], bfr[nf][1], baddr);
                        MMA_BF16(acc[0][nf], a0r[0], a0r[1], a0r[2], a0r[3], bfr[nf][0], bfr[nf][1]);
                        MMA_BF16(acc[1][nf], a1r[0], a1r[1], a1r[2], a1r[3], bfr[nf][0], bfr[nf][1]);
                    }
                }
            } else if (act0) {
#pragma unroll
                for (int ks = 0; ks < 8; ++ks) {
                    const int kk = ks * 16;
                    const int kg = kcol + kk;
                    unsigned a0r[4], bfr[2][2];
                    unsigned addr0 = abase +
                        (unsigned)(((rb0 + (lane & 15)) * ASTR + kk + ((lane >> 4) << 3)) * 2);
                    LDMATRIX_X4(a0r[0], a0r[1], a0r[2], a0r[3], addr0);
#pragma unroll
                    for (int nf = 0; nf < 2; ++nf) {
                        int n = wn * 16 + nf * 8 + (lane >> 2);
                        unsigned baddr = ws_u +
                            (unsigned)((n * WS_STRIDE + kg) * 2) + ((lane & 3) << 3);
                        LDS64(bfr[nf][0], bfr[nf][1], baddr);
                        MMA_BF16(acc[0][nf], a0r[0], a0r[1], a0r[2], a0r[3], bfr[nf][0], bfr[nf][1]);
                    }
                }
            }
        }
        // in-register LSTM cell (each thread owns 4 gates of unit u_loc)

        __nv_bfloat16 hb[4];
#pragma unroll
        for (int mi = 0; mi < 2; ++mi)
#pragma unroll
            for (int h2 = 0; h2 < 2; ++h2) {
                const int li = 2 * mi + h2;
                const int r  = rown[li];
                float gi = acc[mi][0][2 * h2]     + __bfloat162float(Gb[r * GBSTR + u_loc]);
                float gf = acc[mi][0][2 * h2 + 1] + __bfloat162float(Gb[r * GBSTR + 16 + u_loc]);
                float gg = acc[mi][1][2 * h2]     + __bfloat162float(Gb[r * GBSTR + 32 + u_loc]);
                float go = acc[mi][1][2 * h2 + 1] + __bfloat162float(Gb[r * GBSTR + 48 + u_loc]);
                float ii = sigmoidf_(gi);
                float ff = sigmoidf_(gf);
                float gt = tanhf_(gg);
                float oo = sigmoidf_(go);
                float cn = ff * creg[li] + ii * gt;
                float hn = oo * tanhf_(cn);
                bool  m  = t < lenr[li];
                float h2v = m ? hn : hreg[li];
                creg[li] = m ? cn : creg[li];
                hreg[li] = h2v;
                hb[li] = __float2bfloat16(h2v);
                if (t <= lenr[li])
                    h_nxt[(b0 + r) * HID + hid0 + u_loc] = hb[li];
            }

        // publish step t: one barrier, tid0 gpu fence + flag store
        __syncthreads();
        if (tid == 0) {
            asm volatile("membar.gl;" ::: "memory");
            __stcg(&g_flag[bid << 2], t + 1);
        }

        // g_Hall: off critical path
#pragma unroll
        for (int li = 0; li < 4; ++li) {
            if (t < lenr[li]) {
                int r = rown[li];
                g_Hall[((size_t)t * BATCH + b0 + r) * HID + hid0 + u_loc] = hb[li];
            }
        }
    }
}

// ---------------- FC head: logits + binary expansion ----------------
__global__ void __launch_bounds__(128)
fc_kernel(const int* __restrict__ lens, const float* __restrict__ bfc,
          float* __restrict__ out)
{
    __shared__ __nv_bfloat16 As[64 * FC_ASTR];
    __shared__ __nv_bfloat16 Bs[88 * FC_ASTR];

    const int tid  = threadIdx.x;
    const int lane = tid & 31, wid = tid >> 5;
    const int r0   = blockIdx.x * 64;

    float acc[11][4];
#pragma unroll
    for (int i = 0; i < 11; ++i)
#pragma unroll
        for (int j = 0; j < 4; ++j) acc[i][j] = 0.f;

    const unsigned as_u = smem_u32(As);
    const unsigned bs_u = smem_u32(Bs);

    for (int ch = 0; ch < 16; ++ch) {
        __syncthreads();
        const int k0 = ch * 64;
        for (int i = tid; i < 512; i += 128) {
            int row = i >> 3, c8 = i & 7;
            uint4 v = *(reinterpret_cast<const uint4*>(
                    g_Hall + (size_t)(r0 + row) * HID + k0) + c8);
            *(reinterpret_cast<uint4*>(As + row * FC_ASTR) + c8) = v;
        }
        for (int i = tid; i < 704; i += 128) {
            int row = i >> 3, c8 = i & 7;
            uint4 v = *(reinterpret_cast<const uint4*>(
                    g_Wfcb + (size_t)row * HID + k0) + c8);
            *(reinterpret_cast<uint4*>(Bs + row * FC_ASTR) + c8) = v;
        }
        __syncthreads();
#pragma unroll
        for (int ks = 0; ks < 4; ++ks) {
            int kk = ks * 16;
            unsigned a0, a1, a2, a3;
            unsigned addr = as_u +
                (unsigned)(((wid * 16 + (lane & 15)) * FC_ASTR + kk + ((lane >> 4) << 3)) * 2);
            LDMATRIX_X4(a0, a1, a2, a3, addr);
#pragma unroll
            for (int nf = 0; nf < 11; ++nf) {
                int n = nf * 8 + (lane >> 2);
                unsigned baddr = bs_u +
                    (unsigned)((n * FC_ASTR + kk + ((lane & 3) << 1)) * 2);
                unsigned b0r, b1r;
                asm volatile("ld.shared.b32 %0, [%1];" : "=r"(b0r) : "r"(baddr));
                asm volatile("ld.shared.b32 %0, [%1];" : "=r"(b1r) : "r"(baddr + 16));
                MMA_BF16(acc[nf], a0, a1, a2, a3, b0r, b1r);
            }
        }
    }

#pragma unroll
    for (int half = 0; half < 2; ++half) {
        int r  = wid * 16 + (lane >> 2) + half * 8;
        int tb = r0 + r;
        int t  = tb >> 7;
        int b  = tb & 127;
        bool m = t < __ldg(lens + b);
        size_t obase = ((size_t)b * T_STEPS + t) * CLS * 2;
#pragma unroll
        for (int nf = 0; nf < 11; ++nf) {
            int c = nf * 8 + ((lane & 3) << 1);
            float l0 = acc[nf][half * 2 + 0] + __ldg(bfc + c);
            float l1 = acc[nf][half * 2 + 1] + __ldg(bfc + c + 1);
            if (!m) { l0 = 0.f; l1 = 0.f; }
            float4 v = make_float4(l0, 1.f - l0, l1, 1.f - l1);
            *reinterpret_cast<float4*>(out + obase + (size_t)c * 2) = v;
        }
    }
}

// ---------------- launch ----------------
extern "C" void kernel_launch(void* const* d_in, const int* in_sizes, int n_in,
                              void* d_out, int out_size) {
    const float* x    = (const float*)d_in[0];
    const int*   lens = (const int*)d_in[1];    // int32 (JAX x64 disabled)
    const float* Wih  = (const float*)d_in[2];
    const float* Whh  = (const float*)d_in[3];
    const float* bih  = (const float*)d_in[4];
    const float* bhh  = (const float*)d_in[5];
    const float* Wfc  = (const float*)d_in[6];
    const float* bfc  = (const float*)d_in[7];
    float*       out  = (float*)d_out;
    (void)in_sizes; (void)n_in; (void)out_size;

    // launch order: init(1), prep_all(2), gx(3), lstm(4 = ncu slot), fc(5)
    init_kernel<<<64, 256>>>();
    {
        size_t tot = (size_t)T_STEPS * BATCH * FEAT;
        prep_all_kernel<<<(unsigned)((tot + 255) / 256), 256>>>(x, Wih, Whh, bih, bhh, Wfc);
    }
    {
        int gx_smem = (64 * 104 + 256 * 104) * 2;      // 66,560 B
        cudaFuncSetAttribute(gx_kernel, cudaFuncAttributeMaxDynamicSharedMemorySize, gx_smem);
        gx_kernel<<<(T_STEPS * BATCH) / 64, 256, gx_smem>>>();
    }

    int smem = 64 * WS_STRIDE * 2          // resident W slice   (132,096)
             + NBUF * 64 * ASTR * 2        // A-stage ring       (69,632)
             + 64 * GBSTR * 2              // gx slice           (9,216)
             + 64 * 4;                     // lengths
    cudaFuncSetAttribute(lstm_kernel, cudaFuncAttributeMaxDynamicSharedMemorySize, smem);
    lstm_kernel<<<NCTA, NTHR, smem>>>(lens);

    fc_kernel<<<(T_STEPS * BATCH) / 64, 128>>>(lens, bfc, out);
}

// round 17
// speedup vs baseline: 1.3810x; 1.0130x over previous
#include <cuda_runtime.h>
#include <cuda_bf16.h>
#include <cstdint>

#define T_STEPS 1024
#define BATCH   128
#define FEAT    88
#define HID     1024
#define CLS     88
#define NCTA    128
#define NTHR    256
#define MT      64            // batch rows per CTA
#define UPC     16            // hidden units per CTA -> 64 gate cols
#define CW      256           // h chunk width (K cols)  [R17: 128 -> 256]
#define NCHK    4             // chunks per step
#define WS_STRIDE 1032        // resident-W row stride (halfs)
#define ASTR    264           // A-tile row stride (halfs) = CW + 8
#define NBUF    2
#define GBSTR   72            // gx-slice row stride (halfs)
#define FC_ASTR 72

// ---------------- device globals ----------------
__device__ __nv_bfloat16 g_Wc[(size_t)4096 * HID];                 // bf16 W_hh
__device__ __nv_bfloat16 g_Wxb[(size_t)4096 * 96];                 // bf16 W_ih padded to 96
__device__ __nv_bfloat16 g_Wfcb[(size_t)CLS * HID];
__device__ float         g_bsum[4096];
__device__ __nv_bfloat16 g_xb[(size_t)T_STEPS * BATCH * FEAT];
__device__ __nv_bfloat16 g_gx[(size_t)T_STEPS * BATCH * 4096];     // precomputed x@Wih^T + bias
__device__ __nv_bfloat16 g_h[2][BATCH * HID];
__device__ __nv_bfloat16 g_Hall[(size_t)T_STEPS * BATCH * HID];
__device__ int           g_flag[NCTA * 4];

// ---------------- helpers ----------------
__device__ __forceinline__ unsigned smem_u32(const void* p) {
    return (unsigned)__cvta_generic_to_shared(p);
}
__device__ __forceinline__ float sigmoidf_(float x) {
    return 1.0f / (1.0f + __expf(-x));
}
__device__ __forceinline__ float tanhf_(float x) {
    float ax = fabsf(x);
    float e  = __expf(-2.0f * ax);
    float r  = (1.0f - e) / (1.0f + e);
    return (x < 0.0f) ? -r : r;
}

#define MMA_BF16(ACC, A0, A1, A2, A3, B0, B1)                                             \
    asm volatile(                                                                         \
        "mma.sync.aligned.m16n8k16.row.col.f32.bf16.bf16.f32 "                            \
        "{%0,%1,%2,%3}, {%4,%5,%6,%7}, {%8,%9}, {%0,%1,%2,%3};\n"                         \
        : "+f"((ACC)[0]), "+f"((ACC)[1]), "+f"((ACC)[2]), "+f"((ACC)[3])                  \
        : "r"(A0), "r"(A1), "r"(A2), "r"(A3), "r"(B0), "r"(B1))

#define LDMATRIX_X4(R0, R1, R2, R3, ADDR)                                                 \
    asm volatile("ldmatrix.sync.aligned.m8n8.x4.shared.b16 {%0,%1,%2,%3}, [%4];\n"        \
                 : "=r"(R0), "=r"(R1), "=r"(R2), "=r"(R3) : "r"(ADDR))

#define LDS64(R0, R1, ADDR)                                                               \
    asm volatile("ld.shared.v2.u32 {%0,%1}, [%2];" : "=r"(R0), "=r"(R1) : "r"(ADDR))

#define CP_ASYNC16(DST, SRC)                                                              \
    asm volatile("cp.async.cg.shared.global [%0], [%1], 16;\n" :: "r"(DST), "l"(SRC))
#define CP_COMMIT  asm volatile("cp.async.commit_group;\n")
#define CP_WAIT(N) asm volatile("cp.async.wait_group %0;\n" :: "n"(N))

// ---------------- prep kernels (launch order: init, prep_all, gx, lstm(4th), fc) ----------------
__global__ void init_kernel() {
    int idx = blockIdx.x * blockDim.x + threadIdx.x;
    uint4 z = make_uint4(0u, 0u, 0u, 0u);
    for (int i = idx; i < 32768; i += gridDim.x * blockDim.x)
        reinterpret_cast<uint4*>(g_h)[i] = z;
    if (idx < NCTA * 4) g_flag[idx] = 0;
}

__global__ void prep_all_kernel(const float* __restrict__ x,
                                const float* __restrict__ Wih, const float* __restrict__ Whh,
                                const float* __restrict__ bih, const float* __restrict__ bhh,
                                const float* __restrict__ Wfc) {
    size_t idx = (size_t)blockIdx.x * blockDim.x + threadIdx.x;
    if (idx < (size_t)4096 * HID)
        g_Wc[idx] = __float2bfloat16(Whh[idx]);
    if (idx < (size_t)4096 * 96) {
        int n = (int)(idx / 96), k = (int)(idx % 96);
        float v = (k < FEAT) ? Wih[(size_t)n * FEAT + k] : 0.f;
        g_Wxb[idx] = __float2bfloat16(v);
    }
    if (idx < 4096) g_bsum[idx] = bih[idx] + bhh[idx];
    if (idx < (size_t)CLS * HID) g_Wfcb[idx] = __float2bfloat16(Wfc[idx]);
    if (idx < (size_t)T_STEPS * BATCH * FEAT)
        g_xb[idx] = __float2bfloat16(x[idx]);
}

// gx = x @ Wih^T + bsum, bf16. grid = 2048 row-tiles (64 rows), 256 threads.
__global__ void __launch_bounds__(256)
gx_kernel()
{
    extern __shared__ char gs[];
    __nv_bfloat16* Ax = reinterpret_cast<__nv_bfloat16*>(gs);            // 64 x 104
    __nv_bfloat16* Bw = Ax + 64 * 104;                                   // 256 x 104

    const int tid  = threadIdx.x;
    const int lane = tid & 31, wid = tid >> 5;
    const int r0   = blockIdx.x * 64;
    const int rowt = (wid & 3) * 16;
    const int colg = (wid >> 2) * 128;

    const unsigned ax_u = smem_u32(Ax);
    const unsigned bw_u = smem_u32(Bw);

    for (int i = tid; i < 64 * 4; i += 256)
        reinterpret_cast<unsigned*>(Ax)[(i >> 2) * 52 + 44 + (i & 3)] = 0u;
    for (int i = tid; i < 64 * 11; i += 256) {
        int row = i / 11, seg = i % 11;
        unsigned dst = ax_u + (unsigned)((row * 104 + seg * 8) * 2);
        CP_ASYNC16(dst, g_xb + (size_t)(r0 + row) * FEAT + seg * 8);
    }
    CP_COMMIT;

    for (int ci = 0; ci < 16; ++ci) {
        const int c0 = ci * 256;
        for (int i = tid; i < 256 * 12; i += 256) {
            int row = i / 12, seg = i % 12;
            unsigned dst = bw_u + (unsigned)((row * 104 + seg * 8) * 2);
            CP_ASYNC16(dst, g_Wxb + (size_t)(c0 + row) * 96 + seg * 8);
        }
        CP_COMMIT;
        CP_WAIT(0);
        __syncthreads();

        float acc[16][4];
#pragma unroll
        for (int i = 0; i < 16; ++i)
#pragma unroll
            for (int j = 0; j < 4; ++j) acc[i][j] = 0.f;

#pragma unroll
        for (int ks = 0; ks < 6; ++ks) {
            int kk = ks * 16;
            unsigned a0, a1, a2, a3;
            unsigned addr = ax_u +
                (unsigned)(((rowt + (lane & 15)) * 104 + kk + ((lane >> 4) << 3)) * 2);
            LDMATRIX_X4(a0, a1, a2, a3, addr);
#pragma unroll
            for (int nf = 0; nf < 16; ++nf) {
                int n = colg + nf * 8 + (lane >> 2);
                unsigned baddr = bw_u + (unsigned)((n * 104 + kk + ((lane & 3) << 1)) * 2);
                unsigned b0r, b1r;
                asm volatile("ld.shared.b32 %0, [%1];" : "=r"(b0r) : "r"(baddr));
                asm volatile("ld.shared.b32 %0, [%1];" : "=r"(b1r) : "r"(baddr + 16));
                MMA_BF16(acc[nf], a0, a1, a2, a3, b0r, b1r);
            }
        }
        __syncthreads();

#pragma unroll
        for (int half = 0; half < 2; ++half) {
            int r = rowt + (lane >> 2) + half * 8;
            size_t rbase = (size_t)(r0 + r) * 4096;
#pragma unroll
            for (int nf = 0; nf < 16; ++nf) {
                int c = c0 + colg + nf * 8 + ((lane & 3) << 1);
                float v0 = acc[nf][half * 2 + 0] + __ldg(g_bsum + c);
                float v1 = acc[nf][half * 2 + 1] + __ldg(g_bsum + c + 1);
                __nv_bfloat162 b2 = __floats2bfloat162_rn(v0, v1);
                *reinterpret_cast<unsigned*>(&g_gx[rbase + c]) =
                    *reinterpret_cast<unsigned*>(&b2);
            }
        }
    }
}

// ---------------- persistent LSTM kernel ----------------
// 9,871-us chassis (in-register cell, balanced rows {0,48}/{16,32}, LDS64,
// two-phase barrier) with ONE change: CW=256 -> 4 chunks/step, NBUF=2.
// Per chunk: CP_WAIT(0) -> sync -> stage(s+1) -> 16-ks compute. stage(s+1)
// writes the buffer consumed in compute(s-1); the sync orders all its readers
// before the new writes.
__global__ void __launch_bounds__(NTHR, 1)
lstm_kernel(const int* __restrict__ lens)
{
    extern __shared__ char smem_raw[];
    __nv_bfloat16* Ws  = reinterpret_cast<__nv_bfloat16*>(smem_raw);        // 64 * WS_STRIDE
    __nv_bfloat16* As  = Ws + 64 * WS_STRIDE;                               // NBUF * 64 * ASTR
    __nv_bfloat16* Gb  = As + NBUF * 64 * ASTR;                             // 64 * GBSTR
    int*   len_s       = reinterpret_cast<int*>(Gb + 64 * GBSTR);           // 64

    const int tid   = threadIdx.x;
    const int bid   = blockIdx.x;
    const int cta_m = bid & 1;
    const int cta_n = bid >> 1;
    const int b0    = cta_m * MT;
    const int hid0  = cta_n * UPC;

    // resident W slice with (gate,unit) column permutation + k-pair permutation
    for (int i = tid; i < 64 * (HID / 2); i += NTHR) {
        int n = i / (HID / 2), j = i % (HID / 2);
        int g16 = j >> 3, q = j & 7;
        int sp  = (q >> 1) + ((q & 1) << 2);
        int g = (n & 1) + 2 * ((n >> 3) & 1);
        int u = 4 * (n >> 4) + ((n >> 1) & 3);
        const unsigned* src = reinterpret_cast<const unsigned*>(
                g_Wc + (size_t)(g * HID + hid0 + u) * HID);
        reinterpret_cast<unsigned*>(Ws + (size_t)n * WS_STRIDE)[j] = src[g16 * 8 + sp];
    }
    if (tid < 64) len_s[tid] = lens[b0 + tid];
    __syncthreads();

    const int lane = tid & 31, wid = tid >> 5;
    const int wm = wid & 1;        // 0..1
    const int wn = wid >> 1;       // 0..3 : units 4wn..4wn+3
    const int u_loc = 4 * wn + (lane & 3);

    // balanced row blocks: wm0 -> {0, 48}, wm1 -> {16, 32}
    const int rb0 = 16 * wm;
    const int rb1 = 48 - 16 * wm;

    const unsigned ws_u = smem_u32(Ws);
    const unsigned as_u = smem_u32(As);
    const unsigned gb_u = smem_u32(Gb);

    const bool watcher = (tid < 64);
    int* const my_fp   = &g_flag[(((tid & 63) << 1) | cta_m) << 2];

    const int len0 = len_s[0];
    const int lt0  = len_s[rb0];
    const int lt1  = len_s[rb1];

    int rown[4], lenr[4];
#pragma unroll
    for (int mi = 0; mi < 2; ++mi)
#pragma unroll
        for (int h2 = 0; h2 < 2; ++h2) {
            int r = (mi == 0 ? rb0 : rb1) + (lane >> 2) + 8 * h2;
            rown[2 * mi + h2] = r;
            lenr[2 * mi + h2] = len_s[r];
        }

    float hreg[4] = {0.f, 0.f, 0.f, 0.f};
    float creg[4] = {0.f, 0.f, 0.f, 0.f};

    for (int t = 0; t < T_STEPS; ++t) {
        const __nv_bfloat16* __restrict__ h_cur = g_h[t & 1];
        __nv_bfloat16* __restrict__ h_nxt = g_h[(t & 1) ^ 1];

        // whole-CTA early exit: all rows of this half frozen
        if (t >= len0) {
            if (tid == 0) {
                asm volatile("membar.gl;" ::: "memory");
                __stcg(&g_flag[bid << 2], T_STEPS);
            }
            CP_WAIT(0);
            break;
        }

        // stage gx slice for step t (h-independent, pre-barrier)
        {
#pragma unroll
            for (int r = 0; r < 2; ++r) {
                int slot = tid + r * NTHR;          // 0..511 = 64 rows x 8 segs
                int row = slot >> 3, seg = slot & 7;
                int g = seg >> 1, half8 = seg & 1;
                unsigned dst = gb_u + (unsigned)((row * GBSTR + g * 16 + half8 * 8) * 2);
                CP_ASYNC16(dst, g_gx + ((size_t)t * BATCH + b0 + row) * 4096 +
                                g * HID + hid0 + half8 * 8);
            }
            CP_COMMIT;
        }

        // stage chunk s (1..4, CW=256 cols) into buf s&1
        auto stage = [&](int s) {
            unsigned dstb = as_u + (unsigned)((s & 1) * 64 * ASTR * 2);
#pragma unroll
            for (int r = 0; r < 8; ++r) {
                int slot = tid + r * NTHR;          // 2048 slots = 64 rows x 32 seg
                int row = slot >> 5, c16 = slot & 31;
                unsigned dst = dstb + (unsigned)((row * ASTR + c16 * 8) * 2);
                CP_ASYNC16(dst, h_cur + (size_t)(b0 + row) * HID + (s - 1) * CW + c16 * 8);
            }
            CP_COMMIT;
        };

        // two-phase half-barrier (phase A: chunk-1's 16 producers = cta_n 0..15)
        if (t > 0) {
            int fv = 0x7fffffff;
            if (watcher)
                asm volatile("ld.acquire.gpu.global.b32 %0, [%1];" : "=r"(fv) : "l"(my_fp) : "memory");
            for (;;) {
                if (__syncthreads_count((tid >= 16) || (fv >= t)) == NTHR) break;
                if (tid < 16 && fv < t)
                    asm volatile("ld.acquire.gpu.global.b32 %0, [%1];" : "=r"(fv) : "l"(my_fp) : "memory");
            }
            stage(1);                               // c1 load overlaps phase B
            for (;;) {
                if (__syncthreads_count(fv >= t) == NTHR) break;
                if (watcher && fv < t)
                    asm volatile("ld.acquire.gpu.global.b32 %0, [%1];" : "=r"(fv) : "l"(my_fp) : "memory");
            }
        } else {
            stage(1);
        }

        float acc[2][2][4];
#pragma unroll
        for (int a = 0; a < 2; ++a)
#pragma unroll
            for (int b = 0; b < 2; ++b)
#pragma unroll
                for (int c = 0; c < 4; ++c) acc[a][b][c] = 0.f;

        const bool act1 = (t < lt1);
        const bool act0 = (t < lt0);

#pragma unroll
        for (int s = 1; s <= NCHK; ++s) {
            CP_WAIT(0);                 // chunk s data complete (nothing younger yet)
            __syncthreads();            // visible to all; prev buffer fully consumed
            if (s < NCHK) stage(s + 1);

            const int kcol = (s - 1) * CW;
            const unsigned abase = as_u + (unsigned)((s & 1) * 64 * ASTR * 2);

            if (act1) {
#pragma unroll
                for (int ks = 0; ks < 16; ++ks) {
                    const int kk = ks * 16;
                    const int kg = kcol + kk;
                    unsigned a0r[4], a1r[4], bfr[2][2];
                    unsigned addr0 = abase +
                        (unsigned)(((rb0 + (lane & 15)) * ASTR + kk + ((lane >> 4) << 3)) * 2);
                    LDMATRIX_X4(a0r[0], a0r[1], a0r[2], a0r[3], addr0);
                    LDMATRIX_X4(a1r[0], a1r[1], a1r[2], a1r[3],
                                addr0 + (unsigned)((rb1 - rb0) * ASTR * 2));
#pragma unroll
                    for (int nf = 0; nf < 2; ++nf) {
                        int n = wn * 16 + nf * 8 + (lane >> 2);
                        unsigned baddr = ws_u +
                            (unsigned)((n * WS_STRIDE + kg) * 2) + ((lane & 3) << 3);
                        LDS64(bfr[nf][0], bfr[nf][1], baddr);
                        MMA_BF16(acc[0][nf], a0r[0], a0r[1], a0r[2], a0r[3], bfr[nf][0], bfr[nf][1]);
                        MMA_BF16(acc[1][nf], a1r[0], a1r[1], a1r[2], a1r[3], bfr[nf][0], bfr[nf][1]);
                    }
                }
            } else if (act0) {
#pragma unroll
                for (int ks = 0; ks < 16; ++ks) {
                    const int kk = ks * 16;
                    const int kg = kcol + kk;
                    unsigned a0r[4], bfr[2][2];
                    unsigned addr0 = abase +
                        (unsigned)(((rb0 + (lane & 15)) * ASTR + kk + ((lane >> 4) << 3)) * 2);
                    LDMATRIX_X4(a0r[0], a0r[1], a0r[2], a0r[3], addr0);
#pragma unroll
                    for (int nf = 0; nf < 2; ++nf) {
                        int n = wn * 16 + nf * 8 + (lane >> 2);
                        unsigned baddr = ws_u +
                            (unsigned)((n * WS_STRIDE + kg) * 2) + ((lane & 3) << 3);
                        LDS64(bfr[nf][0], bfr[nf][1], baddr);
                        MMA_BF16(acc[0][nf], a0r[0], a0r[1], a0r[2], a0r[3], bfr[nf][0], bfr[nf][1]);
                    }
                }
            }
        }
        // in-register LSTM cell (each thread owns 4 gates of unit u_loc)

        __nv_bfloat16 hb[4];
#pragma unroll
        for (int mi = 0; mi < 2; ++mi)
#pragma unroll
            for (int h2 = 0; h2 < 2; ++h2) {
                const int li = 2 * mi + h2;
                const int r  = rown[li];
                float gi = acc[mi][0][2 * h2]     + __bfloat162float(Gb[r * GBSTR + u_loc]);
                float gf = acc[mi][0][2 * h2 + 1] + __bfloat162float(Gb[r * GBSTR + 16 + u_loc]);
                float gg = acc[mi][1][2 * h2]     + __bfloat162float(Gb[r * GBSTR + 32 + u_loc]);
                float go = acc[mi][1][2 * h2 + 1] + __bfloat162float(Gb[r * GBSTR + 48 + u_loc]);
                float ii = sigmoidf_(gi);
                float ff = sigmoidf_(gf);
                float gt = tanhf_(gg);
                float oo = sigmoidf_(go);
                float cn = ff * creg[li] + ii * gt;
                float hn = oo * tanhf_(cn);
                bool  m  = t < lenr[li];
                float h2v = m ? hn : hreg[li];
                creg[li] = m ? cn : creg[li];
                hreg[li] = h2v;
                hb[li] = __float2bfloat16(h2v);
                if (t <= lenr[li])
                    h_nxt[(b0 + r) * HID + hid0 + u_loc] = hb[li];
            }

        // publish step t: one barrier, tid0 gpu fence + flag store
        __syncthreads();
        if (tid == 0) {
            asm volatile("membar.gl;" ::: "memory");
            __stcg(&g_flag[bid << 2], t + 1);
        }

        // g_Hall: off critical path
#pragma unroll
        for (int li = 0; li < 4; ++li) {
            if (t < lenr[li]) {
                int r = rown[li];
                g_Hall[((size_t)t * BATCH + b0 + r) * HID + hid0 + u_loc] = hb[li];
            }
        }
    }
}

// ---------------- FC head: logits + binary expansion ----------------
__global__ void __launch_bounds__(128)
fc_kernel(const int* __restrict__ lens, const float* __restrict__ bfc,
          float* __restrict__ out)
{
    __shared__ __nv_bfloat16 As[64 * FC_ASTR];
    __shared__ __nv_bfloat16 Bs[88 * FC_ASTR];

    const int tid  = threadIdx.x;
    const int lane = tid & 31, wid = tid >> 5;
    const int r0   = blockIdx.x * 64;

    float acc[11][4];
#pragma unroll
    for (int i = 0; i < 11; ++i)
#pragma unroll
        for (int j = 0; j < 4; ++j) acc[i][j] = 0.f;

    const unsigned as_u = smem_u32(As);
    const unsigned bs_u = smem_u32(Bs);

    for (int ch = 0; ch < 16; ++ch) {
        __syncthreads();
        const int k0 = ch * 64;
        for (int i = tid; i < 512; i += 128) {
            int row = i >> 3, c8 = i & 7;
            uint4 v = *(reinterpret_cast<const uint4*>(
                    g_Hall + (size_t)(r0 + row) * HID + k0) + c8);
            *(reinterpret_cast<uint4*>(As + row * FC_ASTR) + c8) = v;
        }
        for (int i = tid; i < 704; i += 128) {
            int row = i >> 3, c8 = i & 7;
            uint4 v = *(reinterpret_cast<const uint4*>(
                    g_Wfcb + (size_t)row * HID + k0) + c8);
            *(reinterpret_cast<uint4*>(Bs + row * FC_ASTR) + c8) = v;
        }
        __syncthreads();
#pragma unroll
        for (int ks = 0; ks < 4; ++ks) {
            int kk = ks * 16;
            unsigned a0, a1, a2, a3;
            unsigned addr = as_u +
                (unsigned)(((wid * 16 + (lane & 15)) * FC_ASTR + kk + ((lane >> 4) << 3)) * 2);
            LDMATRIX_X4(a0, a1, a2, a3, addr);
#pragma unroll
            for (int nf = 0; nf < 11; ++nf) {
                int n = nf * 8 + (lane >> 2);
                unsigned baddr = bs_u +
                    (unsigned)((n * FC_ASTR + kk + ((lane & 3) << 1)) * 2);
                unsigned b0r, b1r;
                asm volatile("ld.shared.b32 %0, [%1];" : "=r"(b0r) : "r"(baddr));
                asm volatile("ld.shared.b32 %0, [%1];" : "=r"(b1r) : "r"(baddr + 16));
                MMA_BF16(acc[nf], a0, a1, a2, a3, b0r, b1r);
            }
        }
    }

#pragma unroll
    for (int half = 0; half < 2; ++half) {
        int r  = wid * 16 + (lane >> 2) + half * 8;
        int tb = r0 + r;
        int t  = tb >> 7;
        int b  = tb & 127;
        bool m = t < __ldg(lens + b);
        size_t obase = ((size_t)b * T_STEPS + t) * CLS * 2;
#pragma unroll
        for (int nf = 0; nf < 11; ++nf) {
            int c = nf * 8 + ((lane & 3) << 1);
            float l0 = acc[nf][half * 2 + 0] + __ldg(bfc + c);
            float l1 = acc[nf][half * 2 + 1] + __ldg(bfc + c + 1);
            if (!m) { l0 = 0.f; l1 = 0.f; }
            float4 v = make_float4(l0, 1.f - l0, l1, 1.f - l1);
            *reinterpret_cast<float4*>(out + obase + (size_t)c * 2) = v;
        }
    }
}

// ---------------- launch ----------------
extern "C" void kernel_launch(void* const* d_in, const int* in_sizes, int n_in,
                              void* d_out, int out_size) {
    const float* x    = (const float*)d_in[0];
    const int*   lens = (const int*)d_in[1];    // int32 (JAX x64 disabled)
    const float* Wih  = (const float*)d_in[2];
    const float* Whh  = (const float*)d_in[3];
    const float* bih  = (const float*)d_in[4];
    const float* bhh  = (const float*)d_in[5];
    const float* Wfc  = (const float*)d_in[6];
    const float* bfc  = (const float*)d_in[7];
    float*       out  = (float*)d_out;
    (void)in_sizes; (void)n_in; (void)out_size;

    // launch order: init(1), prep_all(2), gx(3), lstm(4 = ncu slot), fc(5)
    init_kernel<<<64, 256>>>();
    {
        size_t tot = (size_t)T_STEPS * BATCH * FEAT;
        prep_all_kernel<<<(unsigned)((tot + 255) / 256), 256>>>(x, Wih, Whh, bih, bhh, Wfc);
    }
    {
        int gx_smem = (64 * 104 + 256 * 104) * 2;      // 66,560 B
        cudaFuncSetAttribute(gx_kernel, cudaFuncAttributeMaxDynamicSharedMemorySize, gx_smem);
        gx_kernel<<<(T_STEPS * BATCH) / 64, 256, gx_smem>>>();
    }

    int smem = 64 * WS_STRIDE * 2          // resident W slice   (132,096)
             + NBUF * 64 * ASTR * 2        // A-stage buffers    (67,584)
             + 64 * GBSTR * 2              // gx slice           (9,216)
             + 64 * 4;                     // lengths
    cudaFuncSetAttribute(lstm_kernel, cudaFuncAttributeMaxDynamicSharedMemorySize, smem);
    lstm_kernel<<<NCTA, NTHR, smem>>>(lens);

    fc_kernel<<<(T_STEPS * BATCH) / 64, 128>>>(lens, bfc, out);
}